// round 3
// baseline (speedup 1.0000x reference)
#include <cuda_runtime.h>
#include <cstdint>

#define NN 100000
#define NR 3
#define NE 300000

// ---- device scratch (no allocs allowed) ----
__device__ float g_m [ (size_t)NN * 128 ];   // transformed features (per-relation, reused)
__device__ float g_h1[ (size_t)NN * 128 ];   // layer-1 accumulator (pre-ReLU)
__device__ float g_outd[ NR * NN ];          // out-degree^-1/2 per relation
__device__ float g_ind [ NR * NN ];          // in-degree^-1/2 per relation

// ------------------------------------------------------------------
__global__ void k_zero_deg() {
    int i = blockIdx.x * blockDim.x + threadIdx.x;
    if (i < NR * NN) { g_outd[i] = 0.f; g_ind[i] = 0.f; }
}

// edges is int32 on device (JAX x64 disabled): layout [NR][2][NE]
__global__ void k_count(const int* __restrict__ E) {
    int i = blockIdx.x * blockDim.x + threadIdx.x;
    if (i >= NR * NE) return;
    int r = i / NE, e = i % NE;
    const int* Er = E + (size_t)r * 2 * NE;
    int src = Er[e];
    int dst = Er[NE + e];
    atomicAdd(&g_outd[r * NN + src], 1.f);
    atomicAdd(&g_ind [r * NN + dst], 1.f);
}

__global__ void k_finalize_deg() {
    int i = blockIdx.x * blockDim.x + threadIdx.x;
    if (i < NR * NN) {
        g_outd[i] = 1.f / sqrtf(fmaxf(g_outd[i], 1.f));
        g_ind [i] = 1.f / sqrtf(fmaxf(g_ind [i], 1.f));
    }
}

// h1[n][f] = b1[0][f] + b1[1][f] + b1[2][f]
__global__ void k_init_h1(const float* __restrict__ b1) {
    int i = blockIdx.x * blockDim.x + threadIdx.x;
    if (i < NN * 128) {
        int f = i & 127;
        g_h1[i] = b1[f] + b1[128 + f] + b1[256 + f];
    }
}

__global__ void k_init_out(float* __restrict__ out, const float* __restrict__ b2) {
    int i = blockIdx.x * blockDim.x + threadIdx.x;
    if (i < NN * 64) {
        int f = i & 63;
        out[i] = b2[f] + b2[64 + f] + b2[128 + f];
    }
}

__global__ void k_relu_out(float* __restrict__ out) {
    int i = blockIdx.x * blockDim.x + threadIdx.x;
    if (i < NN * 64) out[i] = fmaxf(out[i], 0.f);
}

// ------------------------------------------------------------------
// M[row][c] = sum_k (relu?(X[row][k]) * rs[row]) * W[k][c]
// Block tile: ROWS x NOUT, each thread 4x4 outputs. K chunked by 64.
template<int NOUT, int ROWS>
__global__ __launch_bounds__(256) void k_gemm(
    const float* __restrict__ X, const float* __restrict__ W,
    const float* __restrict__ rs, float* __restrict__ M, int relu_in)
{
    constexpr int KC = 64;
    constexpr int CQ = NOUT / 4;
    __shared__ float Ws[KC][NOUT];
    __shared__ float xs[ROWS][KC];

    int tid = threadIdx.x;
    int tc = tid % CQ;
    int tr = tid / CQ;
    int row0 = blockIdx.x * ROWS;

    float acc[4][4] = {};

    for (int k0 = 0; k0 < 128; k0 += KC) {
        // load W chunk [KC x NOUT] (vectorized)
        for (int t = tid; t < KC * NOUT / 4; t += 256) {
            int kk = t / (NOUT / 4);
            int cq = t % (NOUT / 4);
            *(float4*)&Ws[kk][cq * 4] =
                *(const float4*)&W[(size_t)(k0 + kk) * NOUT + cq * 4];
        }
        // load X chunk [ROWS x KC], scaled (+ optional relu)
        for (int t = tid; t < ROWS * KC / 4; t += 256) {
            int rr = t / (KC / 4);
            int kq = t % (KC / 4);
            int row = row0 + rr;
            float4 v = make_float4(0.f, 0.f, 0.f, 0.f);
            if (row < NN) {
                v = *(const float4*)&X[(size_t)row * 128 + k0 + kq * 4];
                if (relu_in) {
                    v.x = fmaxf(v.x, 0.f); v.y = fmaxf(v.y, 0.f);
                    v.z = fmaxf(v.z, 0.f); v.w = fmaxf(v.w, 0.f);
                }
                float s = rs[row];
                v.x *= s; v.y *= s; v.z *= s; v.w *= s;
            }
            *(float4*)&xs[rr][kq * 4] = v;
        }
        __syncthreads();

        #pragma unroll 8
        for (int kk = 0; kk < KC; kk++) {
            float a0 = xs[tr * 4 + 0][kk];
            float a1 = xs[tr * 4 + 1][kk];
            float a2 = xs[tr * 4 + 2][kk];
            float a3 = xs[tr * 4 + 3][kk];
            float4 b = *(const float4*)&Ws[kk][tc * 4];
            acc[0][0] += a0 * b.x; acc[0][1] += a0 * b.y; acc[0][2] += a0 * b.z; acc[0][3] += a0 * b.w;
            acc[1][0] += a1 * b.x; acc[1][1] += a1 * b.y; acc[1][2] += a1 * b.z; acc[1][3] += a1 * b.w;
            acc[2][0] += a2 * b.x; acc[2][1] += a2 * b.y; acc[2][2] += a2 * b.z; acc[2][3] += a2 * b.w;
            acc[3][0] += a3 * b.x; acc[3][1] += a3 * b.y; acc[3][2] += a3 * b.z; acc[3][3] += a3 * b.w;
        }
        __syncthreads();
    }

    #pragma unroll
    for (int i = 0; i < 4; i++) {
        int row = row0 + tr * 4 + i;
        if (row < NN) {
            float4 o = make_float4(acc[i][0], acc[i][1], acc[i][2], acc[i][3]);
            *(float4*)&M[(size_t)row * NOUT + tc * 4] = o;
        }
    }
}

// ------------------------------------------------------------------
// For each edge e of relation r: out[dst] += m[src] * ind[dst]
// Each thread handles a 4-float chunk: vector load, 4 scalar atomic adds.
template<int F>
__global__ __launch_bounds__(256) void k_scatter(
    const int* __restrict__ E, int r,
    const float* __restrict__ ind, const float* __restrict__ m,
    float* __restrict__ out)
{
    constexpr int TPE = F / 4;          // threads per edge
    int t = blockIdx.x * blockDim.x + threadIdx.x;
    int e = t / TPE;
    int lane = t % TPE;
    if (e >= NE) return;
    const int* Er = E + (size_t)r * 2 * NE;
    int src = Er[e];
    int dst = Er[NE + e];
    float s = ind[dst];
    float4 v = *(const float4*)(m + (size_t)src * F + lane * 4);
    float* p = out + (size_t)dst * F + lane * 4;
    atomicAdd(p + 0, v.x * s);
    atomicAdd(p + 1, v.y * s);
    atomicAdd(p + 2, v.z * s);
    atomicAdd(p + 3, v.w * s);
}

// ------------------------------------------------------------------
extern "C" void kernel_launch(void* const* d_in, const int* in_sizes, int n_in,
                              void* d_out, int out_size)
{
    const float* x  = (const float*)d_in[0];
    const float* W1 = (const float*)d_in[1];
    const float* b1 = (const float*)d_in[2];
    const float* W2 = (const float*)d_in[3];
    const float* b2 = (const float*)d_in[4];
    const int*   E  = (const int*)d_in[5];   // int32: JAX x64 disabled
    float* out = (float*)d_out;

    float *pm, *ph1, *poutd, *pind;
    cudaGetSymbolAddress((void**)&pm,    g_m);
    cudaGetSymbolAddress((void**)&ph1,   g_h1);
    cudaGetSymbolAddress((void**)&poutd, g_outd);
    cudaGetSymbolAddress((void**)&pind,  g_ind);

    const int T = 256;

    // degrees (shared by both layers)
    k_zero_deg<<<(NR * NN + T - 1) / T, T>>>();
    k_count<<<(NR * NE + T - 1) / T, T>>>(E);
    k_finalize_deg<<<(NR * NN + T - 1) / T, T>>>();

    // ---- layer 1: h1 = sum_r A'_r (x * od_r) W1_r + sum_r b1_r ----
    k_init_h1<<<(NN * 128 + T - 1) / T, T>>>(b1);
    for (int r = 0; r < NR; r++) {
        k_gemm<128, 32><<<(NN + 31) / 32, 256>>>(
            x, W1 + (size_t)r * 128 * 128, poutd + r * NN, pm, 0);
        k_scatter<128><<<(NE * 32 + T - 1) / T, T>>>(E, r, pind + r * NN, pm, ph1);
    }

    // ---- layer 2: out = sum_r A'_r (relu(h1) * od_r) W2_r + sum_r b2_r ----
    k_init_out<<<(NN * 64 + T - 1) / T, T>>>(out, b2);
    for (int r = 0; r < NR; r++) {
        k_gemm<64, 64><<<(NN + 63) / 64, 256>>>(
            ph1, W2 + (size_t)r * 128 * 64, poutd + r * NN, pm, 1);
        k_scatter<64><<<(NE * 16 + T - 1) / T, T>>>(E, r, pind + r * NN, pm, out);
    }

    // final ReLU
    k_relu_out<<<(NN * 64 + T - 1) / T, T>>>(out);
}

// round 4
// speedup vs baseline: 1.5466x; 1.5466x over previous
#include <cuda_runtime.h>
#include <cstdint>

#define NN 100000
#define NR 3
#define NE 300000

// ---- device scratch (no allocs allowed) ----
__device__ float g_z  [(size_t)NN * 384];   // fused transformed feats (L1: stride 384, L2 reuse: stride 192)
__device__ float g_h1 [(size_t)NN * 128];   // layer-1 output (pre-ReLU)
__device__ float g_outd[NR * NN];           // out-degree^-1/2
__device__ float g_ind [NR * NN];           // in-degree^-1/2
__device__ int   g_cnt_in [NR * NN];        // in-degree histogram
__device__ int   g_cnt_out[NR * NN];        // out-degree histogram
__device__ int   g_off[NR * NN];            // CSR start offsets (into g_csr)
__device__ int   g_cur[NR * NN];            // fill cursors
__device__ int   g_csr[NR * NE];            // src lists grouped by (r,dst)
__device__ int   g_cursor;                  // global slot cursor

// ------------------------------------------------------------------
__global__ void k_zero() {
    int i = blockIdx.x * blockDim.x + threadIdx.x;
    if (i < NR * NN) { g_cnt_in[i] = 0; g_cnt_out[i] = 0; }
    if (i == 0) g_cursor = 0;
}

// edges: int32, layout [NR][2][NE]
__global__ void k_hist(const int* __restrict__ E) {
    int i = blockIdx.x * blockDim.x + threadIdx.x;
    if (i >= NR * NE) return;
    int r = i / NE, e = i % NE;
    const int* Er = E + (size_t)r * 2 * NE;
    atomicAdd(&g_cnt_out[r * NN + Er[e]],      1);
    atomicAdd(&g_cnt_in [r * NN + Er[NE + e]], 1);
}

__global__ void k_finalize_deg() {
    int i = blockIdx.x * blockDim.x + threadIdx.x;
    if (i < NR * NN) {
        g_outd[i] = rsqrtf(fmaxf((float)g_cnt_out[i], 1.f));
        g_ind [i] = rsqrtf(fmaxf((float)g_cnt_in [i], 1.f));
    }
}

// reserve contiguous CSR ranges per (r,dst) via warp-aggregated atomic
__global__ void k_reserve() {
    int i = blockIdx.x * blockDim.x + threadIdx.x;
    int lane = threadIdx.x & 31;
    int d = (i < NR * NN) ? g_cnt_in[i] : 0;
    int s = d;                                // warp inclusive scan
    #pragma unroll
    for (int o = 1; o < 32; o <<= 1) {
        int t = __shfl_up_sync(0xffffffffu, s, o);
        if (lane >= o) s += t;
    }
    int total = __shfl_sync(0xffffffffu, s, 31);
    int base = 0;
    if (lane == 31) base = atomicAdd(&g_cursor, total);
    base = __shfl_sync(0xffffffffu, base, 31);
    if (i < NR * NN) {
        int start = base + s - d;             // exclusive
        g_off[i] = start;
        g_cur[i] = start;
    }
}

__global__ void k_fill(const int* __restrict__ E) {
    int i = blockIdx.x * blockDim.x + threadIdx.x;
    if (i >= NR * NE) return;
    int r = i / NE, e = i % NE;
    const int* Er = E + (size_t)r * 2 * NE;
    int src = Er[e];
    int dst = Er[NE + e];
    int slot = atomicAdd(&g_cur[r * NN + dst], 1);
    g_csr[slot] = src;
}

// ------------------------------------------------------------------
// Z[row][r*NOUT + c] = outd_r[row] * sum_k relu?(X[row][k]) * W[r][k][c]
// grid.y = relation r. Block: ROWS x NOUT, thread 4x4 tile, K chunked by 64.
template<int NOUT, int ROWS, int OSTRIDE>
__global__ __launch_bounds__(256) void k_gemm(
    const float* __restrict__ X, const float* __restrict__ W,
    const float* __restrict__ outd, float* __restrict__ Z, int relu_in)
{
    constexpr int KC = 64;
    constexpr int CQ = NOUT / 4;
    __shared__ float Ws[KC][NOUT];
    __shared__ float xs[ROWS][KC];

    int r = blockIdx.y;
    const float* Wr = W + (size_t)r * 128 * NOUT;
    const float* rs = outd + (size_t)r * NN;

    int tid = threadIdx.x;
    int tc = tid % CQ;
    int tr = tid / CQ;
    int row0 = blockIdx.x * ROWS;

    float acc[4][4] = {};

    for (int k0 = 0; k0 < 128; k0 += KC) {
        for (int t = tid; t < KC * NOUT / 4; t += 256) {
            int kk = t / (NOUT / 4);
            int cq = t % (NOUT / 4);
            *(float4*)&Ws[kk][cq * 4] =
                *(const float4*)&Wr[(size_t)(k0 + kk) * NOUT + cq * 4];
        }
        for (int t = tid; t < ROWS * KC / 4; t += 256) {
            int rr = t / (KC / 4);
            int kq = t % (KC / 4);
            int row = row0 + rr;
            float4 v = make_float4(0.f, 0.f, 0.f, 0.f);
            if (row < NN) {
                v = *(const float4*)&X[(size_t)row * 128 + k0 + kq * 4];
                if (relu_in) {
                    v.x = fmaxf(v.x, 0.f); v.y = fmaxf(v.y, 0.f);
                    v.z = fmaxf(v.z, 0.f); v.w = fmaxf(v.w, 0.f);
                }
            }
            *(float4*)&xs[rr][kq * 4] = v;
        }
        __syncthreads();

        #pragma unroll 8
        for (int kk = 0; kk < KC; kk++) {
            float a0 = xs[tr * 4 + 0][kk];
            float a1 = xs[tr * 4 + 1][kk];
            float a2 = xs[tr * 4 + 2][kk];
            float a3 = xs[tr * 4 + 3][kk];
            float4 b = *(const float4*)&Ws[kk][tc * 4];
            acc[0][0] += a0 * b.x; acc[0][1] += a0 * b.y; acc[0][2] += a0 * b.z; acc[0][3] += a0 * b.w;
            acc[1][0] += a1 * b.x; acc[1][1] += a1 * b.y; acc[1][2] += a1 * b.z; acc[1][3] += a1 * b.w;
            acc[2][0] += a2 * b.x; acc[2][1] += a2 * b.y; acc[2][2] += a2 * b.z; acc[2][3] += a2 * b.w;
            acc[3][0] += a3 * b.x; acc[3][1] += a3 * b.y; acc[3][2] += a3 * b.z; acc[3][3] += a3 * b.w;
        }
        __syncthreads();
    }

    #pragma unroll
    for (int i = 0; i < 4; i++) {
        int row = row0 + tr * 4 + i;
        if (row < NN) {
            float s = rs[row];
            float4 o = make_float4(acc[i][0] * s, acc[i][1] * s, acc[i][2] * s, acc[i][3] * s);
            *(float4*)&Z[(size_t)row * OSTRIDE + r * NOUT + tc * 4] = o;
        }
    }
}

// ------------------------------------------------------------------
// Gather (layer 1): one warp per dst. h1[dst][f] = sum_r b1[r][f] + ind_r[dst]*sum_e z[src][r*128+f]
__global__ __launch_bounds__(256) void k_gather128(
    const float* __restrict__ Z, const float* __restrict__ b1,
    float* __restrict__ O)
{
    int w = (blockIdx.x * blockDim.x + threadIdx.x) >> 5;
    int lane = threadIdx.x & 31;
    if (w >= NN) return;

    float4 tot = make_float4(0.f, 0.f, 0.f, 0.f);
    #pragma unroll
    for (int r = 0; r < NR; r++) {
        float4 b = *(const float4*)&b1[r * 128 + lane * 4];
        tot.x += b.x; tot.y += b.y; tot.z += b.z; tot.w += b.w;

        int idx = r * NN + w;
        int start = g_off[idx];
        int n = g_cnt_in[idx];
        float4 acc = make_float4(0.f, 0.f, 0.f, 0.f);
        for (int j = 0; j < n; j++) {
            int src = g_csr[start + j];
            float4 v = *(const float4*)&Z[(size_t)src * 384 + r * 128 + lane * 4];
            acc.x += v.x; acc.y += v.y; acc.z += v.z; acc.w += v.w;
        }
        float s = g_ind[idx];
        tot.x += s * acc.x; tot.y += s * acc.y; tot.z += s * acc.z; tot.w += s * acc.w;
    }
    *(float4*)&O[(size_t)w * 128 + lane * 4] = tot;
}

// Gather (layer 2): warp per dst, lane covers 2 floats. Final ReLU fused.
__global__ __launch_bounds__(256) void k_gather64(
    const float* __restrict__ Z, const float* __restrict__ b2,
    float* __restrict__ O)
{
    int w = (blockIdx.x * blockDim.x + threadIdx.x) >> 5;
    int lane = threadIdx.x & 31;
    if (w >= NN) return;

    float2 tot = make_float2(0.f, 0.f);
    #pragma unroll
    for (int r = 0; r < NR; r++) {
        float2 b = *(const float2*)&b2[r * 64 + lane * 2];
        tot.x += b.x; tot.y += b.y;

        int idx = r * NN + w;
        int start = g_off[idx];
        int n = g_cnt_in[idx];
        float2 acc = make_float2(0.f, 0.f);
        for (int j = 0; j < n; j++) {
            int src = g_csr[start + j];
            float2 v = *(const float2*)&Z[(size_t)src * 192 + r * 64 + lane * 2];
            acc.x += v.x; acc.y += v.y;
        }
        float s = g_ind[idx];
        tot.x += s * acc.x; tot.y += s * acc.y;
    }
    float2 o = make_float2(fmaxf(tot.x, 0.f), fmaxf(tot.y, 0.f));
    *(float2*)&O[(size_t)w * 64 + lane * 2] = o;
}

// ------------------------------------------------------------------
extern "C" void kernel_launch(void* const* d_in, const int* in_sizes, int n_in,
                              void* d_out, int out_size)
{
    const float* x  = (const float*)d_in[0];
    const float* W1 = (const float*)d_in[1];
    const float* b1 = (const float*)d_in[2];
    const float* W2 = (const float*)d_in[3];
    const float* b2 = (const float*)d_in[4];
    const int*   E  = (const int*)d_in[5];   // int32 (JAX x64 disabled)
    float* out = (float*)d_out;

    float *pz, *ph1, *poutd;
    cudaGetSymbolAddress((void**)&pz,    g_z);
    cudaGetSymbolAddress((void**)&ph1,   g_h1);
    cudaGetSymbolAddress((void**)&poutd, g_outd);

    const int T = 256;

    // ---- CSR + degree build (shared by both layers) ----
    k_zero        <<<(NR * NN + T - 1) / T, T>>>();
    k_hist        <<<(NR * NE + T - 1) / T, T>>>(E);
    k_finalize_deg<<<(NR * NN + T - 1) / T, T>>>();
    k_reserve     <<<(NR * NN + T - 1) / T, T>>>();
    k_fill        <<<(NR * NE + T - 1) / T, T>>>(E);

    // ---- layer 1 ----
    k_gemm<128, 32, 384><<<dim3((NN + 31) / 32, NR), 256>>>(x, W1, poutd, pz, 0);
    k_gather128<<<(NN * 32 + T - 1) / T, T>>>(pz, b1, ph1);

    // ---- layer 2 ----
    k_gemm<64, 64, 192><<<dim3((NN + 63) / 64, NR), 256>>>(ph1, W2, poutd, pz, 1);
    k_gather64<<<(NN * 32 + T - 1) / T, T>>>(pz, b2, out);
}

// round 5
// speedup vs baseline: 1.6627x; 1.0751x over previous
#include <cuda_runtime.h>
#include <cstdint>

#define NN 100000
#define NR 3
#define NE 300000

// ---- device scratch (no allocs allowed) ----
__device__ float g_z  [(size_t)NN * 384];   // fused transformed feats
__device__ float g_h1 [(size_t)NN * 128];   // layer-1 output (pre-ReLU)
__device__ float g_outd[NR * NN];           // out-degree^-1/2
__device__ float g_ind [NR * NN];           // in-degree^-1/2
__device__ int   g_cnt_in [NR * NN];
__device__ int   g_cnt_out[NR * NN];
__device__ int   g_off[NR * NN];
__device__ int   g_cur[NR * NN];
__device__ int   g_csr[NR * NE];
__device__ int   g_cursor;

// ------------------------------------------------------------------
__global__ void k_zero() {
    int i = blockIdx.x * blockDim.x + threadIdx.x;
    if (i < NR * NN) { g_cnt_in[i] = 0; g_cnt_out[i] = 0; }
    if (i == 0) g_cursor = 0;
}

__global__ void k_hist(const int* __restrict__ E) {
    int i = blockIdx.x * blockDim.x + threadIdx.x;
    if (i >= NR * NE) return;
    int r = i / NE, e = i % NE;
    const int* Er = E + (size_t)r * 2 * NE;
    atomicAdd(&g_cnt_out[r * NN + Er[e]],      1);
    atomicAdd(&g_cnt_in [r * NN + Er[NE + e]], 1);
}

__global__ void k_finalize_deg() {
    int i = blockIdx.x * blockDim.x + threadIdx.x;
    if (i < NR * NN) {
        g_outd[i] = rsqrtf(fmaxf((float)g_cnt_out[i], 1.f));
        g_ind [i] = rsqrtf(fmaxf((float)g_cnt_in [i], 1.f));
    }
}

__global__ void k_reserve() {
    int i = blockIdx.x * blockDim.x + threadIdx.x;
    int lane = threadIdx.x & 31;
    int d = (i < NR * NN) ? g_cnt_in[i] : 0;
    int s = d;
    #pragma unroll
    for (int o = 1; o < 32; o <<= 1) {
        int t = __shfl_up_sync(0xffffffffu, s, o);
        if (lane >= o) s += t;
    }
    int total = __shfl_sync(0xffffffffu, s, 31);
    int base = 0;
    if (lane == 31) base = atomicAdd(&g_cursor, total);
    base = __shfl_sync(0xffffffffu, base, 31);
    if (i < NR * NN) {
        int start = base + s - d;
        g_off[i] = start;
        g_cur[i] = start;
    }
}

__global__ void k_fill(const int* __restrict__ E) {
    int i = blockIdx.x * blockDim.x + threadIdx.x;
    if (i >= NR * NE) return;
    int r = i / NE, e = i % NE;
    const int* Er = E + (size_t)r * 2 * NE;
    int src = Er[e];
    int dst = Er[NE + e];
    int slot = atomicAdd(&g_cur[r * NN + dst], 1);
    g_csr[slot] = src;
}

// ------------------------------------------------------------------
__device__ __forceinline__ uint32_t f2tf32(float x) {
    uint32_t r;
    asm("cvt.rna.tf32.f32 %0, %1;" : "=r"(r) : "f"(x));
    return r;
}

__device__ __forceinline__ void mma_tf32(float* c, const uint32_t* a, const uint32_t* b) {
    asm volatile(
        "mma.sync.aligned.m16n8k8.row.col.f32.tf32.tf32.f32 "
        "{%0,%1,%2,%3}, {%4,%5,%6,%7}, {%8,%9}, {%0,%1,%2,%3};"
        : "+f"(c[0]), "+f"(c[1]), "+f"(c[2]), "+f"(c[3])
        : "r"(a[0]), "r"(a[1]), "r"(a[2]), "r"(a[3]),
          "r"(b[0]), "r"(b[1]));
}

// Z[row][rel*BN + c] = outd_rel[row] * sum_k relu?(X[row][k]) * W[rel][k][c]
// Tensor-core tf32 3-pass split GEMM. Block tile 128 x BN, 8 warps (4M x 2N).
template<int BN, int OSTRIDE>
__global__ __launch_bounds__(256) void k_gemm_tc(
    const float* __restrict__ X, const float* __restrict__ W,
    const float* __restrict__ outd, float* __restrict__ Z, int relu_in)
{
    constexpr int BM = 128, KC = 16;
    constexpr int PA = 4, PB = 4;
    constexpr int WN = BN / 2;      // per-warp N tile
    constexpr int NFR = WN / 8;     // N frags per warp

    __shared__ uint32_t xhi[KC][BM + PA], xlo[KC][BM + PA];
    __shared__ uint32_t whi[KC][BN + PB], wlo[KC][BN + PB];

    int rel = blockIdx.y;
    const float* Wr = W + (size_t)rel * 128 * BN;
    const float* rs = outd + (size_t)rel * NN;
    int row0 = blockIdx.x * BM;
    int tid  = threadIdx.x;
    int warp = tid >> 5, lane = tid & 31;
    int wm = warp & 3, wn = warp >> 2;
    int m_w = wm * 32, n_w = wn * WN;

    float acc[2][NFR][4];
    #pragma unroll
    for (int i = 0; i < 2; i++)
        #pragma unroll
        for (int j = 0; j < NFR; j++)
            #pragma unroll
            for (int q = 0; q < 4; q++) acc[i][j][q] = 0.f;

    for (int k0 = 0; k0 < 128; k0 += KC) {
        // X tile [BM x KC] -> smem [k][row], split hi/lo
        #pragma unroll
        for (int t = tid; t < BM * KC / 4; t += 256) {
            int rr = t / (KC / 4);
            int kq = t % (KC / 4);
            int row = row0 + rr;
            float4 v = make_float4(0.f, 0.f, 0.f, 0.f);
            if (row < NN) {
                v = *(const float4*)&X[(size_t)row * 128 + k0 + kq * 4];
                if (relu_in) {
                    v.x = fmaxf(v.x, 0.f); v.y = fmaxf(v.y, 0.f);
                    v.z = fmaxf(v.z, 0.f); v.w = fmaxf(v.w, 0.f);
                }
            }
            const float* pv = &v.x;
            #pragma unroll
            for (int u = 0; u < 4; u++) {
                float f = pv[u];
                uint32_t hi = f2tf32(f);
                float lo = f - __uint_as_float(hi);
                xhi[kq * 4 + u][rr] = hi;
                xlo[kq * 4 + u][rr] = f2tf32(lo);
            }
        }
        // W tile [KC x BN] -> smem [k][n], split hi/lo
        #pragma unroll
        for (int t = tid; t < KC * BN / 4; t += 256) {
            int kk = t / (BN / 4);
            int nq = t % (BN / 4);
            float4 v = *(const float4*)&Wr[(size_t)(k0 + kk) * BN + nq * 4];
            const float* pv = &v.x;
            #pragma unroll
            for (int u = 0; u < 4; u++) {
                float f = pv[u];
                uint32_t hi = f2tf32(f);
                float lo = f - __uint_as_float(hi);
                whi[kk][nq * 4 + u] = hi;
                wlo[kk][nq * 4 + u] = f2tf32(lo);
            }
        }
        __syncthreads();

        #pragma unroll
        for (int k8 = 0; k8 < KC; k8 += 8) {
            uint32_t ah[2][4], al[2][4];
            int ar = lane >> 2;
            int ac = k8 + (lane & 3);
            #pragma unroll
            for (int i = 0; i < 2; i++) {
                int rb = m_w + i * 16 + ar;
                ah[i][0] = xhi[ac][rb];       al[i][0] = xlo[ac][rb];
                ah[i][1] = xhi[ac][rb + 8];   al[i][1] = xlo[ac][rb + 8];
                ah[i][2] = xhi[ac + 4][rb];   al[i][2] = xlo[ac + 4][rb];
                ah[i][3] = xhi[ac + 4][rb + 8]; al[i][3] = xlo[ac + 4][rb + 8];
            }
            #pragma unroll
            for (int j = 0; j < NFR; j++) {
                int nb = n_w + j * 8 + (lane >> 2);
                int kb = k8 + (lane & 3);
                uint32_t bh[2] = { whi[kb][nb], whi[kb + 4][nb] };
                uint32_t bl[2] = { wlo[kb][nb], wlo[kb + 4][nb] };
                #pragma unroll
                for (int i = 0; i < 2; i++) {
                    mma_tf32(acc[i][j], ah[i], bh);
                    mma_tf32(acc[i][j], ah[i], bl);
                    mma_tf32(acc[i][j], al[i], bh);
                }
            }
        }
        __syncthreads();
    }

    // epilogue: scale by outd, write float2 pairs
    int cr = lane >> 2;
    int cc = (lane & 3) * 2;
    #pragma unroll
    for (int i = 0; i < 2; i++) {
        int r0g = row0 + m_w + i * 16 + cr;
        int r1g = r0g + 8;
        float s0 = (r0g < NN) ? rs[r0g] : 0.f;
        float s1 = (r1g < NN) ? rs[r1g] : 0.f;
        #pragma unroll
        for (int j = 0; j < NFR; j++) {
            int col = rel * BN + n_w + j * 8 + cc;
            if (r0g < NN) {
                float2 o = make_float2(acc[i][j][0] * s0, acc[i][j][1] * s0);
                *(float2*)&Z[(size_t)r0g * OSTRIDE + col] = o;
            }
            if (r1g < NN) {
                float2 o = make_float2(acc[i][j][2] * s1, acc[i][j][3] * s1);
                *(float2*)&Z[(size_t)r1g * OSTRIDE + col] = o;
            }
        }
    }
}

// ------------------------------------------------------------------
__global__ __launch_bounds__(256) void k_gather128(
    const float* __restrict__ Z, const float* __restrict__ b1,
    float* __restrict__ O)
{
    int w = (blockIdx.x * blockDim.x + threadIdx.x) >> 5;
    int lane = threadIdx.x & 31;
    if (w >= NN) return;

    float4 tot = make_float4(0.f, 0.f, 0.f, 0.f);
    #pragma unroll
    for (int r = 0; r < NR; r++) {
        float4 b = *(const float4*)&b1[r * 128 + lane * 4];
        tot.x += b.x; tot.y += b.y; tot.z += b.z; tot.w += b.w;

        int idx = r * NN + w;
        int start = g_off[idx];
        int n = g_cnt_in[idx];
        float4 acc = make_float4(0.f, 0.f, 0.f, 0.f);
        for (int j = 0; j < n; j++) {
            int src = g_csr[start + j];
            float4 v = *(const float4*)&Z[(size_t)src * 384 + r * 128 + lane * 4];
            acc.x += v.x; acc.y += v.y; acc.z += v.z; acc.w += v.w;
        }
        float s = g_ind[idx];
        tot.x += s * acc.x; tot.y += s * acc.y; tot.z += s * acc.z; tot.w += s * acc.w;
    }
    *(float4*)&O[(size_t)w * 128 + lane * 4] = tot;
}

__global__ __launch_bounds__(256) void k_gather64(
    const float* __restrict__ Z, const float* __restrict__ b2,
    float* __restrict__ O)
{
    int w = (blockIdx.x * blockDim.x + threadIdx.x) >> 5;
    int lane = threadIdx.x & 31;
    if (w >= NN) return;

    float2 tot = make_float2(0.f, 0.f);
    #pragma unroll
    for (int r = 0; r < NR; r++) {
        float2 b = *(const float2*)&b2[r * 64 + lane * 2];
        tot.x += b.x; tot.y += b.y;

        int idx = r * NN + w;
        int start = g_off[idx];
        int n = g_cnt_in[idx];
        float2 acc = make_float2(0.f, 0.f);
        for (int j = 0; j < n; j++) {
            int src = g_csr[start + j];
            float2 v = *(const float2*)&Z[(size_t)src * 192 + r * 64 + lane * 2];
            acc.x += v.x; acc.y += v.y;
        }
        float s = g_ind[idx];
        tot.x += s * acc.x; tot.y += s * acc.y;
    }
    float2 o = make_float2(fmaxf(tot.x, 0.f), fmaxf(tot.y, 0.f));
    *(float2*)&O[(size_t)w * 64 + lane * 2] = o;
}

// ------------------------------------------------------------------
extern "C" void kernel_launch(void* const* d_in, const int* in_sizes, int n_in,
                              void* d_out, int out_size)
{
    const float* x  = (const float*)d_in[0];
    const float* W1 = (const float*)d_in[1];
    const float* b1 = (const float*)d_in[2];
    const float* W2 = (const float*)d_in[3];
    const float* b2 = (const float*)d_in[4];
    const int*   E  = (const int*)d_in[5];
    float* out = (float*)d_out;

    float *pz, *ph1, *poutd;
    cudaGetSymbolAddress((void**)&pz,    g_z);
    cudaGetSymbolAddress((void**)&ph1,   g_h1);
    cudaGetSymbolAddress((void**)&poutd, g_outd);

    const int T = 256;

    // CSR + degree build (shared by both layers)
    k_zero        <<<(NR * NN + T - 1) / T, T>>>();
    k_hist        <<<(NR * NE + T - 1) / T, T>>>(E);
    k_finalize_deg<<<(NR * NN + T - 1) / T, T>>>();
    k_reserve     <<<(NR * NN + T - 1) / T, T>>>();
    k_fill        <<<(NR * NE + T - 1) / T, T>>>(E);

    // layer 1
    k_gemm_tc<128, 384><<<dim3((NN + 127) / 128, NR), 256>>>(x, W1, poutd, pz, 0);
    k_gather128<<<(NN * 32 + T - 1) / T, T>>>(pz, b1, ph1);

    // layer 2
    k_gemm_tc<64, 192><<<dim3((NN + 127) / 128, NR), 256>>>(ph1, W2, poutd, pz, 1);
    k_gather64<<<(NN * 32 + T - 1) / T, T>>>(pz, b2, out);
}

// round 6
// speedup vs baseline: 2.2280x; 1.3400x over previous
#include <cuda_runtime.h>
#include <cuda_bf16.h>
#include <cstdint>

#define NN 100000
#define NR 3
#define NE 300000

// ---- device scratch (no allocs allowed) ----
__device__ float g_z  [(size_t)NN * 384];
__device__ float g_h1 [(size_t)NN * 128];
__device__ float g_outd[NR * NN];
__device__ float g_ind [NR * NN];
__device__ int   g_cnt_in [NR * NN];
__device__ int   g_cnt_out[NR * NN];
__device__ int   g_off[NR * NN];
__device__ int   g_cur[NR * NN];
__device__ int   g_csr[NR * NE];
__device__ int   g_cursor;

// ------------------------------------------------------------------
__global__ void k_zero() {
    int i = blockIdx.x * blockDim.x + threadIdx.x;
    if (i < NR * NN) { g_cnt_in[i] = 0; g_cnt_out[i] = 0; }
    if (i == 0) g_cursor = 0;
}

__global__ void k_hist(const int* __restrict__ E) {
    int i = blockIdx.x * blockDim.x + threadIdx.x;
    if (i >= NR * NE) return;
    int r = i / NE, e = i % NE;
    const int* Er = E + (size_t)r * 2 * NE;
    atomicAdd(&g_cnt_out[r * NN + Er[e]],      1);
    atomicAdd(&g_cnt_in [r * NN + Er[NE + e]], 1);
}

__global__ void k_finalize_deg() {
    int i = blockIdx.x * blockDim.x + threadIdx.x;
    if (i < NR * NN) {
        g_outd[i] = rsqrtf(fmaxf((float)g_cnt_out[i], 1.f));
        g_ind [i] = rsqrtf(fmaxf((float)g_cnt_in [i], 1.f));
    }
}

__global__ void k_reserve() {
    int i = blockIdx.x * blockDim.x + threadIdx.x;
    int lane = threadIdx.x & 31;
    int d = (i < NR * NN) ? g_cnt_in[i] : 0;
    int s = d;
    #pragma unroll
    for (int o = 1; o < 32; o <<= 1) {
        int t = __shfl_up_sync(0xffffffffu, s, o);
        if (lane >= o) s += t;
    }
    int total = __shfl_sync(0xffffffffu, s, 31);
    int base = 0;
    if (lane == 31) base = atomicAdd(&g_cursor, total);
    base = __shfl_sync(0xffffffffu, base, 31);
    if (i < NR * NN) {
        int start = base + s - d;
        g_off[i] = start;
        g_cur[i] = start;
    }
}

__global__ void k_fill(const int* __restrict__ E) {
    int i = blockIdx.x * blockDim.x + threadIdx.x;
    if (i >= NR * NE) return;
    int r = i / NE, e = i % NE;
    const int* Er = E + (size_t)r * 2 * NE;
    int src = Er[e];
    int dst = Er[NE + e];
    int slot = atomicAdd(&g_cur[r * NN + dst], 1);
    g_csr[slot] = src;
}

// ------------------------------------------------------------------
// pack two floats (lo=k even, hi=k odd) into bf16x2 register
__device__ __forceinline__ uint32_t pack_bf16x2(float lo, float hi) {
    uint32_t r;
    asm("cvt.rn.bf16x2.f32 %0, %1, %2;" : "=r"(r) : "f"(hi), "f"(lo));
    return r;
}

// split f into bf16 hi + bf16 lo residual
__device__ __forceinline__ void bsplit(float f, float& h, float& l) {
    __nv_bfloat16 bh = __float2bfloat16_rn(f);
    h = __bfloat162float(bh);
    l = f - h;
}

__device__ __forceinline__ void mma_bf16(float* c, const uint32_t* a, const uint32_t* b) {
    asm volatile(
        "mma.sync.aligned.m16n8k16.row.col.f32.bf16.bf16.f32 "
        "{%0,%1,%2,%3}, {%4,%5,%6,%7}, {%8,%9}, {%0,%1,%2,%3};"
        : "+f"(c[0]), "+f"(c[1]), "+f"(c[2]), "+f"(c[3])
        : "r"(a[0]), "r"(a[1]), "r"(a[2]), "r"(a[3]),
          "r"(b[0]), "r"(b[1]));
}

// Z[row][rel*BN + c] = outd_rel[row] * sum_k relu?(X[row][k]) * W[rel][k][c]
// bf16 2-way split (3 mma passes), m16n8k16. Block 128 x BN, 8 warps (4M x 2N).
template<int BN, int OSTRIDE>
__global__ __launch_bounds__(256) void k_gemm_tc(
    const float* __restrict__ X, const float* __restrict__ W,
    const float* __restrict__ outd, float* __restrict__ Z, int relu_in)
{
    constexpr int BM = 128, KC = 32;     // k-chunk (16 bf16x2 pairs)
    constexpr int K2 = KC / 2;
    constexpr int PA = 4, PB = 4;
    constexpr int WN = BN / 2;
    constexpr int NFR = WN / 8;

    __shared__ uint32_t xh[K2][BM + PA], xl[K2][BM + PA];   // [k2][row]
    __shared__ uint32_t wh[K2][BN + PB], wl[K2][BN + PB];   // [k2][n]

    int rel = blockIdx.y;
    const float* Wr = W + (size_t)rel * 128 * BN;
    const float* rs = outd + (size_t)rel * NN;
    int row0 = blockIdx.x * BM;
    int tid  = threadIdx.x;
    int warp = tid >> 5, lane = tid & 31;
    int wm = warp & 3, wn = warp >> 2;
    int m_w = wm * 32, n_w = wn * WN;

    float acc[2][NFR][4];
    #pragma unroll
    for (int i = 0; i < 2; i++)
        #pragma unroll
        for (int j = 0; j < NFR; j++)
            #pragma unroll
            for (int q = 0; q < 4; q++) acc[i][j][q] = 0.f;

    for (int k0 = 0; k0 < 128; k0 += KC) {
        // X tile [BM x KC]: thread loads float4 (4 k's, 1 row) -> 2 packed pairs
        #pragma unroll
        for (int t = tid; t < BM * KC / 4; t += 256) {
            int rr = t / (KC / 4);
            int kq = t % (KC / 4);
            int row = row0 + rr;
            float4 v = make_float4(0.f, 0.f, 0.f, 0.f);
            if (row < NN) {
                v = *(const float4*)&X[(size_t)row * 128 + k0 + kq * 4];
                if (relu_in) {
                    v.x = fmaxf(v.x, 0.f); v.y = fmaxf(v.y, 0.f);
                    v.z = fmaxf(v.z, 0.f); v.w = fmaxf(v.w, 0.f);
                }
            }
            float hx, lx, hy, ly, hz, lz, hw, lw;
            bsplit(v.x, hx, lx); bsplit(v.y, hy, ly);
            bsplit(v.z, hz, lz); bsplit(v.w, hw, lw);
            xh[kq * 2 + 0][rr] = pack_bf16x2(hx, hy);
            xl[kq * 2 + 0][rr] = pack_bf16x2(lx, ly);
            xh[kq * 2 + 1][rr] = pack_bf16x2(hz, hw);
            xl[kq * 2 + 1][rr] = pack_bf16x2(lz, lw);
        }
        // W tile [KC x BN]: thread handles (k2, 4 n's): two rows k, k+1
        #pragma unroll
        for (int t = tid; t < K2 * BN / 4; t += 256) {
            int k2 = t / (BN / 4);
            int nq = t % (BN / 4);
            float4 v0 = *(const float4*)&Wr[(size_t)(k0 + 2 * k2)     * BN + nq * 4];
            float4 v1 = *(const float4*)&Wr[(size_t)(k0 + 2 * k2 + 1) * BN + nq * 4];
            const float* p0 = &v0.x;
            const float* p1 = &v1.x;
            #pragma unroll
            for (int u = 0; u < 4; u++) {
                float h0, l0, h1, l1;
                bsplit(p0[u], h0, l0);
                bsplit(p1[u], h1, l1);
                wh[k2][nq * 4 + u] = pack_bf16x2(h0, h1);
                wl[k2][nq * 4 + u] = pack_bf16x2(l0, l1);
            }
        }
        __syncthreads();

        #pragma unroll
        for (int ks = 0; ks < K2; ks += 8) {   // one m16n8k16 step per 8 pairs
            uint32_t ah[2][4], al[2][4];
            int ar = lane >> 2;
            int ac = ks + (lane & 3);
            #pragma unroll
            for (int i = 0; i < 2; i++) {
                int rb = m_w + i * 16 + ar;
                ah[i][0] = xh[ac][rb];         al[i][0] = xl[ac][rb];
                ah[i][1] = xh[ac][rb + 8];     al[i][1] = xl[ac][rb + 8];
                ah[i][2] = xh[ac + 4][rb];     al[i][2] = xl[ac + 4][rb];
                ah[i][3] = xh[ac + 4][rb + 8]; al[i][3] = xl[ac + 4][rb + 8];
            }
            #pragma unroll
            for (int j = 0; j < NFR; j++) {
                int nb = n_w + j * 8 + (lane >> 2);
                int kb = ks + (lane & 3);
                uint32_t bh[2] = { wh[kb][nb], wh[kb + 4][nb] };
                uint32_t bl[2] = { wl[kb][nb], wl[kb + 4][nb] };
                #pragma unroll
                for (int i = 0; i < 2; i++) {
                    mma_bf16(acc[i][j], ah[i], bh);
                    mma_bf16(acc[i][j], ah[i], bl);
                    mma_bf16(acc[i][j], al[i], bh);
                }
            }
        }
        __syncthreads();
    }

    // epilogue: scale by outd, write float2 pairs
    int cr = lane >> 2;
    int cc = (lane & 3) * 2;
    #pragma unroll
    for (int i = 0; i < 2; i++) {
        int r0g = row0 + m_w + i * 16 + cr;
        int r1g = r0g + 8;
        float s0 = (r0g < NN) ? rs[r0g] : 0.f;
        float s1 = (r1g < NN) ? rs[r1g] : 0.f;
        #pragma unroll
        for (int j = 0; j < NFR; j++) {
            int col = rel * BN + n_w + j * 8 + cc;
            if (r0g < NN) {
                float2 o = make_float2(acc[i][j][0] * s0, acc[i][j][1] * s0);
                *(float2*)&Z[(size_t)r0g * OSTRIDE + col] = o;
            }
            if (r1g < NN) {
                float2 o = make_float2(acc[i][j][2] * s1, acc[i][j][3] * s1);
                *(float2*)&Z[(size_t)r1g * OSTRIDE + col] = o;
            }
        }
    }
}

// ------------------------------------------------------------------
__global__ __launch_bounds__(256) void k_gather128(
    const float* __restrict__ Z, const float* __restrict__ b1,
    float* __restrict__ O)
{
    int w = (blockIdx.x * blockDim.x + threadIdx.x) >> 5;
    int lane = threadIdx.x & 31;
    if (w >= NN) return;

    float4 tot = make_float4(0.f, 0.f, 0.f, 0.f);
    #pragma unroll
    for (int r = 0; r < NR; r++) {
        float4 b = *(const float4*)&b1[r * 128 + lane * 4];
        tot.x += b.x; tot.y += b.y; tot.z += b.z; tot.w += b.w;

        int idx = r * NN + w;
        int start = g_off[idx];
        int n = g_cnt_in[idx];
        float4 acc = make_float4(0.f, 0.f, 0.f, 0.f);
        for (int j = 0; j < n; j++) {
            int src = g_csr[start + j];
            float4 v = *(const float4*)&Z[(size_t)src * 384 + r * 128 + lane * 4];
            acc.x += v.x; acc.y += v.y; acc.z += v.z; acc.w += v.w;
        }
        float s = g_ind[idx];
        tot.x += s * acc.x; tot.y += s * acc.y; tot.z += s * acc.z; tot.w += s * acc.w;
    }
    *(float4*)&O[(size_t)w * 128 + lane * 4] = tot;
}

__global__ __launch_bounds__(256) void k_gather64(
    const float* __restrict__ Z, const float* __restrict__ b2,
    float* __restrict__ O)
{
    int w = (blockIdx.x * blockDim.x + threadIdx.x) >> 5;
    int lane = threadIdx.x & 31;
    if (w >= NN) return;

    float2 tot = make_float2(0.f, 0.f);
    #pragma unroll
    for (int r = 0; r < NR; r++) {
        float2 b = *(const float2*)&b2[r * 64 + lane * 2];
        tot.x += b.x; tot.y += b.y;

        int idx = r * NN + w;
        int start = g_off[idx];
        int n = g_cnt_in[idx];
        float2 acc = make_float2(0.f, 0.f);
        for (int j = 0; j < n; j++) {
            int src = g_csr[start + j];
            float2 v = *(const float2*)&Z[(size_t)src * 192 + r * 64 + lane * 2];
            acc.x += v.x; acc.y += v.y;
        }
        float s = g_ind[idx];
        tot.x += s * acc.x; tot.y += s * acc.y;
    }
    float2 o = make_float2(fmaxf(tot.x, 0.f), fmaxf(tot.y, 0.f));
    *(float2*)&O[(size_t)w * 64 + lane * 2] = o;
}

// ------------------------------------------------------------------
extern "C" void kernel_launch(void* const* d_in, const int* in_sizes, int n_in,
                              void* d_out, int out_size)
{
    const float* x  = (const float*)d_in[0];
    const float* W1 = (const float*)d_in[1];
    const float* b1 = (const float*)d_in[2];
    const float* W2 = (const float*)d_in[3];
    const float* b2 = (const float*)d_in[4];
    const int*   E  = (const int*)d_in[5];
    float* out = (float*)d_out;

    float *pz, *ph1, *poutd;
    cudaGetSymbolAddress((void**)&pz,    g_z);
    cudaGetSymbolAddress((void**)&ph1,   g_h1);
    cudaGetSymbolAddress((void**)&poutd, g_outd);

    const int T = 256;

    // CSR + degree build (shared by both layers)
    k_zero        <<<(NR * NN + T - 1) / T, T>>>();
    k_hist        <<<(NR * NE + T - 1) / T, T>>>(E);
    k_finalize_deg<<<(NR * NN + T - 1) / T, T>>>();
    k_reserve     <<<(NR * NN + T - 1) / T, T>>>();
    k_fill        <<<(NR * NE + T - 1) / T, T>>>(E);

    // layer 1
    k_gemm_tc<128, 384><<<dim3((NN + 127) / 128, NR), 256>>>(x, W1, poutd, pz, 0);
    k_gather128<<<(NN * 32 + T - 1) / T, T>>>(pz, b1, ph1);

    // layer 2
    k_gemm_tc<64, 192><<<dim3((NN + 127) / 128, NR), 256>>>(ph1, W2, poutd, pz, 1);
    k_gather64<<<(NN * 32 + T - 1) / T, T>>>(pz, b2, out);
}